// round 9
// baseline (speedup 1.0000x reference)
#include <cuda_runtime.h>
#include <cuda_bf16.h>
#include <stdint.h>
#include <math.h>

#define B_ 1024
#define T_ 250
#define D_ 158
#define H_ 128
#define G_ 512          // 4*H
#define M_ (B_*T_)      // 256000 rows
#define P_ 64
#define O_ 22

typedef unsigned long long ull;

// ---------------- scratch (device globals: the sanctioned alloc-free path) ----------------
__device__ float g_xn[(size_t)M_ * D_];   // LN output; later reused as layer-1 h output
__device__ float g_xg[(size_t)M_ * G_];   // precomputed input gates for current layer
__device__ float g_h0[(size_t)M_ * H_];   // layer-0 h sequence

// ---------------- f32x2 packed-FMA helpers ----------------
__device__ __forceinline__ void fma2(ull& d, ull a, ull b, ull c) {
    asm("fma.rn.f32x2 %0, %1, %2, %3;" : "=l"(d) : "l"(a), "l"(b), "l"(c));
}
__device__ __forceinline__ ull pack2(float a, float b) {
    ull r; asm("mov.b64 %0, {%1,%2};" : "=l"(r) : "f"(a), "f"(b)); return r;
}
__device__ __forceinline__ float2 upk2(ull v) {
    float2 r; asm("mov.b64 {%0,%1}, %2;" : "=f"(r.x), "=f"(r.y) : "l"(v)); return r;
}
__device__ __forceinline__ uint32_t s2u(const void* p) {
    return (uint32_t)__cvta_generic_to_shared(p);
}
__device__ __forceinline__ void st_remote_u64(uint32_t laddr, uint32_t peer, ull v) {
    uint32_t r;
    asm volatile("mapa.shared::cluster.u32 %0, %1, %2;" : "=r"(r) : "r"(laddr), "r"(peer));
    asm volatile("st.shared::cluster.b64 [%0], %1;" :: "r"(r), "l"(v) : "memory");
}

// ---------------- activation helpers (exact fp32 path) ----------------
__device__ __forceinline__ float sigm_(float x) {
    return 1.f / (1.f + __expf(-x));
}
__device__ __forceinline__ float tanh_fast(float x) {
    float a = fabsf(x);
    float e = __expf(a + a);
    float t = 1.f - 2.f / (e + 1.f);
    return copysignf(t, x);
}

// ---------------- LayerNorm over last dim (158) ----------------
__global__ void __launch_bounds__(256) ln_kernel(const float* __restrict__ x,
                                                 const float* __restrict__ gamma,
                                                 const float* __restrict__ beta,
                                                 float* __restrict__ xn) {
    int row  = blockIdx.x * 8 + (threadIdx.x >> 5);
    int lane = threadIdx.x & 31;
    const float* xr = x + (size_t)row * D_;
    float v[5];
    float s = 0.f, s2 = 0.f;
#pragma unroll
    for (int i = 0; i < 5; i++) {
        int k = lane + 32 * i;
        v[i] = (k < D_) ? xr[k] : 0.f;
        s += v[i];
        s2 = fmaf(v[i], v[i], s2);
    }
#pragma unroll
    for (int o = 16; o; o >>= 1) {
        s  += __shfl_xor_sync(0xffffffffu, s, o);
        s2 += __shfl_xor_sync(0xffffffffu, s2, o);
    }
    float mu  = s * (1.f / D_);
    float var = s2 * (1.f / D_) - mu * mu;
    float inv = rsqrtf(var + 1e-5f);
    float* xo = xn + (size_t)row * D_;
#pragma unroll
    for (int i = 0; i < 5; i++) {
        int k = lane + 32 * i;
        if (k < D_) xo[k] = (v[i] - mu) * inv * gamma[k] + beta[k];
    }
}

// ---------------- FFMA2 GEMM: C[M,512] = A[M,K] * W[512,K]^T + bias ----------------
// BM=128, BN=128, BK=16, 256 threads, 8x8 microtile.
// A stored RAW in smem (32B/thread/kk), duplicated into f32x2 pairs via register
// movs (alu pipe). B read as natural n-pairs. LDS 64B/thread/kk == FFMA2 floor.
template <int K>
__global__ void __launch_bounds__(256, 2) gemm2_kernel(const float* __restrict__ A,
                                                       const float* __restrict__ W,
                                                       const float* __restrict__ bias,
                                                       float* __restrict__ C) {
    __shared__ float As[2][16][128];   // raw A: 16 KB total
    __shared__ float Bs[2][16][128];   // 16 KB
    constexpr int NT = (K + 15) / 16;

    int tid = threadIdx.x;
    int row = tid >> 1;                // 0..127
    int kb  = (tid & 1) * 8;           // 0 or 8
    int m0 = blockIdx.y * 128, n0 = blockIdx.x * 128;
    int tx = tid & 15, ty = tid >> 4;

    const float* Arow = A + (size_t)(m0 + row) * K;
    const float* Wrow = W + (size_t)(n0 + row) * K;

    ull acc[8][4];
#pragma unroll
    for (int i = 0; i < 8; i++)
#pragma unroll
        for (int j = 0; j < 4; j++) acc[i][j] = 0ull;

    float ar[8], br[8];
#pragma unroll
    for (int j = 0; j < 8; j++) {
        int k = kb + j;
        ar[j] = (k < K) ? Arow[k] : 0.f;
        br[j] = (k < K) ? Wrow[k] : 0.f;
    }
#pragma unroll
    for (int j = 0; j < 8; j++) {
        As[0][kb + j][row] = ar[j];
        Bs[0][kb + j][row] = br[j];
    }
    __syncthreads();

    for (int tIdx = 0; tIdx < NT; tIdx++) {
        int cur = tIdx & 1, nxt = cur ^ 1;
        if (tIdx + 1 < NT) {
            int k0 = (tIdx + 1) * 16;
#pragma unroll
            for (int j = 0; j < 8; j++) {
                int k = k0 + kb + j;
                ar[j] = (k < K) ? Arow[k] : 0.f;
                br[j] = (k < K) ? Wrow[k] : 0.f;
            }
        }
#pragma unroll
        for (int kk = 0; kk < 16; kk++) {
            const float* ap = &As[cur][kk][ty * 8];
            float4 av0 = *(const float4*)ap;
            float4 av1 = *(const float4*)(ap + 4);
            const longlong2* bp = (const longlong2*)&Bs[cur][kk][tx * 8];
            longlong2 b03 = bp[0], b47 = bp[1];
            ull au[8];
            au[0] = pack2(av0.x, av0.x); au[1] = pack2(av0.y, av0.y);
            au[2] = pack2(av0.z, av0.z); au[3] = pack2(av0.w, av0.w);
            au[4] = pack2(av1.x, av1.x); au[5] = pack2(av1.y, av1.y);
            au[6] = pack2(av1.z, av1.z); au[7] = pack2(av1.w, av1.w);
            ull bu[4] = {(ull)b03.x, (ull)b03.y, (ull)b47.x, (ull)b47.y};
#pragma unroll
            for (int i = 0; i < 8; i++)
#pragma unroll
                for (int j = 0; j < 4; j++)
                    fma2(acc[i][j], au[i], bu[j], acc[i][j]);
        }
        if (tIdx + 1 < NT) {
#pragma unroll
            for (int j = 0; j < 8; j++) {
                As[nxt][kb + j][row] = ar[j];
                Bs[nxt][kb + j][row] = br[j];
            }
        }
        __syncthreads();
    }

    float bb[8];
#pragma unroll
    for (int j = 0; j < 8; j++) bb[j] = bias[n0 + tx * 8 + j];
#pragma unroll
    for (int i = 0; i < 8; i++) {
        float2 p0 = upk2(acc[i][0]);
        float2 p1 = upk2(acc[i][1]);
        float2 p2 = upk2(acc[i][2]);
        float2 p3 = upk2(acc[i][3]);
        float4 v0 = make_float4(p0.x + bb[0], p0.y + bb[1], p1.x + bb[2], p1.y + bb[3]);
        float4 v1 = make_float4(p2.x + bb[4], p2.y + bb[5], p3.x + bb[6], p3.y + bb[7]);
        float* crow = C + (size_t)(m0 + ty * 8 + i) * G_ + n0 + tx * 8;
        *(float4*)(crow)     = v0;
        *(float4*)(crow + 4) = v1;
    }
}

// ---------------- clustered LSTM recurrence, k-pair dot-product form ----------------
// Cluster of 2 CTAs owns 16 batch rows for all 250 steps. CTA rank c holds W_hh
// rows for its 256 gates {128q+64c+j} in SMEM, pre-packed as k-adjacent f32x2
// pairs (128 KB, zero per-step global traffic). Per step: thread tid owns ONE
// local gate for ALL 16 rows; FFMA2 halves accumulate even/odd k separately
// (no operand duplication), reduced once at the end. h state [2 parity][16
// row][128 k] raw floats; each CTA updates its 64 units and mirrors them into
// the peer via one 8B DSMEM store per row-pair; cluster barrier per step.
// smem: ws4 131072 + hs 16384 + gs 16384 = 163840 B
#define LSTM_SMEM_BYTES (131072 + 16384 + 16384)

__global__ void __launch_bounds__(256) __cluster_dims__(2, 1, 1)
lstm_cluster_kernel(const float* __restrict__ xg,
                    const float* __restrict__ Whh,    // [512][128] row-major
                    float* __restrict__ hout) {
    extern __shared__ ull sm[];
    ull*   ws4 = sm;                       // [32 kp2][256 gate][2] ull = 16384 ull
    float* hs  = (float*)(sm + 16384);     // [2 parity][16 row][128 k]
    float* gs  = hs + 2 * 16 * 128;        // [16 row][256 local gate]

    int tid = threadIdx.x;
    uint32_t crank;
    asm("mov.u32 %0, %%cluster_ctarank;" : "=r"(crank));
    int c = (int)crank;
    int b0 = (blockIdx.x >> 1) * 16;

    int q = tid >> 6, j = tid & 63;
    int g = 128 * q + 64 * c + j;          // this thread's global gate

    // fill ws4[kp2*512 + l*2 + u] = (Whh[g(l)][4kp2+2u], Whh[g(l)][4kp2+2u+1])
    for (int idx = tid; idx < 16384; idx += 256) {
        int kp2 = idx >> 9;
        int rem = idx & 511;
        int l = rem >> 1, u = rem & 1;
        int gg = 128 * (l >> 6) + 64 * c + (l & 63);
        int k0 = 4 * kp2 + 2 * u;
        ws4[idx] = pack2(Whh[gg * 128 + k0], Whh[gg * 128 + k0 + 1]);
    }
    for (int i = tid; i < 2 * 16 * 128; i += 256) hs[i] = 0.f;
    __syncthreads();
    asm volatile("barrier.cluster.arrive.aligned;" ::: "memory");
    asm volatile("barrier.cluster.wait.aligned;" ::: "memory");

    // phase-B mapping: warp wB handles rows wB, wB+8; lane handles local units 2l,2l+1
    int wB = tid >> 5;
    int l2 = (tid & 31) * 2;
    float2 cst[2] = {{0.f, 0.f}, {0.f, 0.f}};

    uint32_t hs_u32 = s2u(hs);
    const float* xgb = xg + (size_t)b0 * T_ * G_ + g;
    const size_t RSTR = (size_t)T_ * G_;

    // prefetch xg for t=0 (one scalar per row)
    float pref[16];
#pragma unroll
    for (int r = 0; r < 16; r++) pref[r] = xgb[(size_t)r * RSTR];

    for (int t = 0; t < T_; t++) {
        int par = t & 1;
        ull acc[16];
#pragma unroll
        for (int r = 0; r < 16; r++) acc[r] = pack2(pref[r], 0.f);
        int tn = (t + 1 < T_) ? (t + 1) : t;
#pragma unroll
        for (int r = 0; r < 16; r++)
            pref[r] = xgb[(size_t)r * RSTR + (size_t)tn * G_];

        const float* hrow = hs + par * 2048;
        const ull* wbase = ws4 + 2 * tid;
#pragma unroll 2
        for (int kp2 = 0; kp2 < 32; kp2++) {
            ulonglong2 w2 = *(const ulonglong2*)(wbase + kp2 * 512);
            const float* hk = hrow + 4 * kp2;
#pragma unroll
            for (int r = 0; r < 16; r++) {
                ulonglong2 h2 = *(const ulonglong2*)(hk + r * 128);
                fma2(acc[r], (ull)w2.x, (ull)h2.x, acc[r]);
                fma2(acc[r], (ull)w2.y, (ull)h2.y, acc[r]);
            }
        }
#pragma unroll
        for (int r = 0; r < 16; r++) {
            float2 p = upk2(acc[r]);
            gs[r * 256 + tid] = p.x + p.y;
        }
        __syncthreads();

        // phase B: activations + state update (gate order i, f, g, o)
        float* hnew = hs + (par ^ 1) * 2048;
        uint32_t hnew_u32 = hs_u32 + (uint32_t)((par ^ 1) * 2048) * 4u;
#pragma unroll
        for (int s = 0; s < 2; s++) {
            int row = wB + 8 * s;
            float2 gi = *(float2*)&gs[row * 256 + l2];
            float2 gf = *(float2*)&gs[row * 256 + 64 + l2];
            float2 gg = *(float2*)&gs[row * 256 + 128 + l2];
            float2 go = *(float2*)&gs[row * 256 + 192 + l2];
            float2 cc = cst[s];
            cc.x = sigm_(gf.x) * cc.x + sigm_(gi.x) * tanh_fast(gg.x);
            cc.y = sigm_(gf.y) * cc.y + sigm_(gi.y) * tanh_fast(gg.y);
            float h0v = sigm_(go.x) * tanh_fast(cc.x);
            float h1v = sigm_(go.y) * tanh_fast(cc.y);
            cst[s] = cc;
            int jj = 64 * c + l2;
            *(float2*)&hnew[row * 128 + jj] = make_float2(h0v, h1v);
            st_remote_u64(hnew_u32 + (uint32_t)(row * 128 + jj) * 4u,
                          (uint32_t)(c ^ 1), pack2(h0v, h1v));
            *(float2*)&hout[((size_t)(b0 + row) * T_ + t) * H_ + jj] = make_float2(h0v, h1v);
        }
        asm volatile("barrier.cluster.arrive.aligned;" ::: "memory");
        asm volatile("barrier.cluster.wait.aligned;" ::: "memory");
    }
}

// ---------------- projection head: ReLU(h @ Wp1^T + bp1) @ Wp2^T + bp2 ----------------
__global__ void __launch_bounds__(256) proj_kernel(const float* __restrict__ h,
                                                   const float* __restrict__ Wp1,
                                                   const float* __restrict__ bp1,
                                                   const float* __restrict__ Wp2,
                                                   const float* __restrict__ bp2,
                                                   float* __restrict__ out) {
    __shared__ float w1t[128][65];
    __shared__ float w2t[64][22];
    __shared__ float ps[32][64];
    __shared__ float b1s[64];
    __shared__ float b2s[22];
    int tid = threadIdx.x;

    for (int i = tid; i < P_ * H_; i += 256) { int jj = i >> 7, kk = i & 127; w1t[kk][jj] = Wp1[i]; }
    for (int i = tid; i < O_ * P_; i += 256) { int oo = i >> 6, kk = i & 63;  w2t[kk][oo] = Wp2[i]; }
    if (tid < P_) b1s[tid] = bp1[tid];
    if (tid < O_) b2s[tid] = bp2[tid];
    __syncthreads();

    size_t row0 = (size_t)blockIdx.x * 32;
    int jj = tid & 63;
    int rs = tid >> 6;
    float acc[8] = {};
    const float* hrow[8];
#pragma unroll
    for (int rr = 0; rr < 8; rr++) hrow[rr] = h + (row0 + (size_t)rs * 8 + rr) * H_;

    for (int k4 = 0; k4 < 32; k4++) {
        float4 hv[8];
#pragma unroll
        for (int rr = 0; rr < 8; rr++) hv[rr] = *(const float4*)(hrow[rr] + 4 * k4);
#pragma unroll
        for (int kk = 0; kk < 4; kk++) {
            float w = w1t[4 * k4 + kk][jj];
#pragma unroll
            for (int rr = 0; rr < 8; rr++) {
                float hvv = (&hv[rr].x)[kk];
                acc[rr] = fmaf(hvv, w, acc[rr]);
            }
        }
    }
#pragma unroll
    for (int rr = 0; rr < 8; rr++) {
        float v = acc[rr] + b1s[jj];
        ps[rs * 8 + rr][jj] = v > 0.f ? v : 0.f;
    }
    __syncthreads();

    for (int idx = tid; idx < 32 * O_; idx += 256) {
        int rr = idx / O_;
        int oo = idx - rr * O_;
        float s = b2s[oo];
#pragma unroll
        for (int k = 0; k < P_; k++) s = fmaf(ps[rr][k], w2t[k][oo], s);
        out[(row0 + rr) * O_ + oo] = s;
    }
}

// ---------------- launch ----------------
extern "C" void kernel_launch(void* const* d_in, const int* in_sizes, int n_in,
                              void* d_out, int out_size) {
    const float* x     = (const float*)d_in[0];
    const float* ln_g  = (const float*)d_in[1];
    const float* ln_b  = (const float*)d_in[2];
    const float* W_ih0 = (const float*)d_in[3];
    const float* W_hh0 = (const float*)d_in[4];
    const float* b0    = (const float*)d_in[5];
    const float* W_ih1 = (const float*)d_in[6];
    const float* W_hh1 = (const float*)d_in[7];
    const float* b1    = (const float*)d_in[8];
    const float* Wp1   = (const float*)d_in[9];
    const float* bp1   = (const float*)d_in[10];
    const float* Wp2   = (const float*)d_in[11];
    const float* bp2   = (const float*)d_in[12];
    float* out = (float*)d_out;

    float *xn, *xg, *h0;
    cudaGetSymbolAddress((void**)&xn, g_xn);
    cudaGetSymbolAddress((void**)&xg, g_xg);
    cudaGetSymbolAddress((void**)&h0, g_h0);
    float* h1 = xn;   // reuse LN buffer for layer-1 h output

    cudaFuncSetAttribute(lstm_cluster_kernel,
                         cudaFuncAttributeMaxDynamicSharedMemorySize, LSTM_SMEM_BYTES);

    ln_kernel<<<M_ / 8, 256>>>(x, ln_g, ln_b, xn);

    gemm2_kernel<D_><<<dim3(4, M_ / 128), 256>>>(xn, W_ih0, b0, xg);
    lstm_cluster_kernel<<<128, 256, LSTM_SMEM_BYTES>>>(xg, W_hh0, h0);

    gemm2_kernel<H_><<<dim3(4, M_ / 128), 256>>>(h0, W_ih1, b1, xg);
    lstm_cluster_kernel<<<128, 256, LSTM_SMEM_BYTES>>>(xg, W_hh1, h1);

    proj_kernel<<<M_ / 32, 256>>>(h1, Wp1, bp1, Wp2, bp2, out);
}